// round 14
// baseline (speedup 1.0000x reference)
#include <cuda_runtime.h>
#include <cuda_fp16.h>
#include <math.h>

#define BB 8
#define NN 1024
#define EMBD 768
#define HEADS 8
#define INNERD 96
#define HEAD_D 12
#define MLP_D 3072
#define ROWS (BB*NN)   // 8192

// ---------------- scratch (no allocations allowed) ----------------
__device__ __half g_h16[ROWS * EMBD];
__device__ float  g_qkv[ROWS * 3 * INNERD];
__device__ __half g_att16[ROWS * INNERD];
__device__ float  g_x1[ROWS * EMBD];
__device__ __half g_mlp16[ROWS * MLP_D];
__device__ __half g_wqkv_t[3 * INNERD * EMBD];
__device__ __half g_wproj_t[EMBD * INNERD];
__device__ __half g_w1_t[MLP_D * EMBD];
__device__ __half g_w2_t[EMBD * MLP_D];

// ---------------- merged weight transpose + fp32->fp16 convert ----------------
__global__ __launch_bounds__(256) void wconv_all(
    const float* s0, __half* d0,
    const float* s1, __half* d1,
    const float* s2, __half* d2,
    const float* s3, __half* d3)
{
    int bid = blockIdx.x;
    const float* src; __half* dst; int K, N, ntx, t;
    if (bid < 216)       { src = s0; dst = d0; K = EMBD;  N = 3*INNERD; ntx = 9;  t = bid; }
    else if (bid < 288)  { src = s1; dst = d1; K = INNERD; N = EMBD;    ntx = 24; t = bid - 216; }
    else if (bid < 2592) { src = s2; dst = d2; K = EMBD;  N = MLP_D;    ntx = 96; t = bid - 288; }
    else                 { src = s3; dst = d3; K = MLP_D; N = EMBD;     ntx = 24; t = bid - 2592; }
    int n0 = (t % ntx) * 32, k0 = (t / ntx) * 32;

    __shared__ float sm[32][33];
    int tx = threadIdx.x & 31, ty = threadIdx.x >> 5;
    #pragma unroll
    for (int i = 0; i < 4; ++i)
        sm[ty + i * 8][tx] = src[(size_t)(k0 + ty + i * 8) * N + n0 + tx];
    __syncthreads();
    #pragma unroll
    for (int i = 0; i < 4; ++i)
        dst[(size_t)(n0 + ty + i * 8) * K + k0 + tx] = __float2half_rn(sm[tx][ty + i * 8]);
}

// ---------------- LayerNorm ----------------
__global__ __launch_bounds__(256) void ln_kernel(const float* __restrict__ x,
                                                 const float* __restrict__ g,
                                                 const float* __restrict__ b,
                                                 __half* __restrict__ out)
{
    int row = blockIdx.x;
    const float* xr = x + (size_t)row * EMBD;
    float s1 = 0.f, s2 = 0.f;
    for (int c = threadIdx.x; c < EMBD; c += 256) {
        float v = xr[c];
        s1 += v; s2 += v * v;
    }
    #pragma unroll
    for (int o = 16; o > 0; o >>= 1) {
        s1 += __shfl_xor_sync(0xFFFFFFFFu, s1, o);
        s2 += __shfl_xor_sync(0xFFFFFFFFu, s2, o);
    }
    __shared__ float sh1[8], sh2[8];
    int w = threadIdx.x >> 5, l = threadIdx.x & 31;
    if (l == 0) { sh1[w] = s1; sh2[w] = s2; }
    __syncthreads();
    float t1 = 0.f, t2 = 0.f;
    #pragma unroll
    for (int i = 0; i < 8; ++i) { t1 += sh1[i]; t2 += sh2[i]; }
    float mu = t1 * (1.f / EMBD);
    float var = t2 * (1.f / EMBD) - mu * mu;
    float rs = rsqrtf(var + 1e-5f);
    __half* orow = out + (size_t)row * EMBD;
    for (int c = threadIdx.x; c < EMBD; c += 256)
        orow[c] = __float2half_rn((xr[c] - mu) * rs * g[c] + b[c]);
}

// ---------------- common mma helpers ----------------
__device__ __forceinline__ float gelu_erf(float v) {
    return 0.5f * v * (1.f + erff(v * 0.70710678118654752f));
}
__device__ __forceinline__ void cp16(unsigned dst, const void* src, int srcBytes) {
    asm volatile("cp.async.cg.shared.global [%0], [%1], 16, %2;"
                 :: "r"(dst), "l"(src), "r"(srcBytes));
}
__device__ __forceinline__ void cp_commit() {
    asm volatile("cp.async.commit_group;");
}
template<int Nw>
__device__ __forceinline__ void cp_wait() {
    asm volatile("cp.async.wait_group %0;" :: "n"(Nw));
}
__device__ __forceinline__ void ldm4(unsigned* r, unsigned addr) {
    asm volatile("ldmatrix.sync.aligned.m8n8.x4.shared.b16 {%0,%1,%2,%3}, [%4];"
                 : "=r"(r[0]), "=r"(r[1]), "=r"(r[2]), "=r"(r[3]) : "r"(addr));
}
__device__ __forceinline__ void mma16816(float* c, const unsigned* a, unsigned b0, unsigned b1) {
    asm volatile(
        "mma.sync.aligned.m16n8k16.row.col.f32.f16.f16.f32 "
        "{%0,%1,%2,%3}, {%4,%5,%6,%7}, {%8,%9}, {%0,%1,%2,%3};"
        : "+f"(c[0]), "+f"(c[1]), "+f"(c[2]), "+f"(c[3])
        : "r"(a[0]), "r"(a[1]), "r"(a[2]), "r"(a[3]), "r"(b0), "r"(b1));
}

// ---------------- fp16 tensor-core GEMM, BM=128, 4-stage cp.async ----------------
#define H_SH 40
#define H_TILE (128 * H_SH)
#define H_STG (2 * H_TILE)
#define H_NSTAGE 4
#define H_SMEM_BYTES (H_NSTAGE * H_STG * 2)

// EPI: 0 = fp32 C; 2 = +bias, exact gelu, fp16 C; 3 = +bias +fp32 residual, fp32 C.
template<int EPI>
__global__ __launch_bounds__(256, 2) void hgemm(
    const __half* __restrict__ A, const __half* __restrict__ Bt,
    const float* __restrict__ bias, const float* __restrict__ res,
    void* __restrict__ Cv, int M, int N, int K)
{
    extern __shared__ __half smh[];
    unsigned sbase = (unsigned)__cvta_generic_to_shared(smh);

    int tid = threadIdx.x;
    int row0 = blockIdx.y * 128, col0 = blockIdx.x * 128;
    int warp = tid >> 5, lane = tid & 31;
    int wm = (warp & 3) * 32, wn = (warp >> 2) * 64;
    int gid = lane >> 2, tig = lane & 3;
    int within = lane & 7, sub = lane >> 3;

    int lr = tid >> 1;
    int lc0 = (tid & 1) * 2;

    const __half* Ag = A + (size_t)(row0 + lr) * K;
    const __half* Bg = Bt + (size_t)(col0 + lr) * K;
    bool bok = (col0 + lr) < N;

    float acc[2][8][4];
    #pragma unroll
    for (int t = 0; t < 2; ++t)
        #pragma unroll
        for (int u = 0; u < 8; ++u)
            #pragma unroll
            for (int v = 0; v < 4; ++v) acc[t][u][v] = 0.f;

    int KT = K >> 5;

    auto issue = [&](int kt) {
        int stg = kt & (H_NSTAGE - 1);
        int koff = kt * 32;
        unsigned abase = sbase + (stg * H_STG) * 2;
        unsigned bbase = abase + H_TILE * 2;
        #pragma unroll
        for (int s = 0; s < 2; ++s) {
            int c = lc0 + s;
            cp16(abase + (lr * H_SH + c * 8) * 2, Ag + koff + c * 8, 16);
            cp16(bbase + (lr * H_SH + c * 8) * 2, Bg + koff + c * 8, bok ? 16 : 0);
        }
        cp_commit();
    };

    issue(0);
    if (KT > 1) issue(1);
    if (KT > 2) issue(2);

    int a_off = (wm + (sub & 1) * 8 + within) * H_SH + (sub >> 1) * 8;
    int b_off = (wn + (sub >> 1) * 8 + within) * H_SH + (sub & 1) * 8;

    for (int kt = 0; kt < KT; ++kt) {
        if (kt + 2 <= KT - 1) cp_wait<2>(); else cp_wait<0>();
        __syncthreads();
        if (kt + 3 < KT) issue(kt + 3);

        unsigned abase = sbase + ((kt & (H_NSTAGE - 1)) * H_STG) * 2;
        unsigned bbase = abase + H_TILE * 2;

        #pragma unroll
        for (int ks = 0; ks < 2; ++ks) {
            int kb = ks * 16;
            unsigned aR[2][4], bR[4][4];
            #pragma unroll
            for (int t = 0; t < 2; ++t)
                ldm4(aR[t], abase + (a_off + t * 16 * H_SH + kb) * 2);
            #pragma unroll
            for (int u = 0; u < 4; ++u)
                ldm4(bR[u], bbase + (b_off + u * 16 * H_SH + kb) * 2);
            #pragma unroll
            for (int t = 0; t < 2; ++t)
                #pragma unroll
                for (int u8 = 0; u8 < 8; ++u8) {
                    int u4 = u8 >> 1, hi = u8 & 1;
                    mma16816(acc[t][u8], aR[t], bR[u4][hi * 2], bR[u4][hi * 2 + 1]);
                }
        }
    }

    #pragma unroll
    for (int t = 0; t < 2; ++t) {
        #pragma unroll
        for (int u = 0; u < 8; ++u) {
            int c = col0 + wn + u * 8 + tig * 2;
            if (c >= N) continue;
            int r0 = row0 + wm + t * 16 + gid;
            float v0 = acc[t][u][0], v1 = acc[t][u][1];
            float v2 = acc[t][u][2], v3 = acc[t][u][3];
            if (EPI >= 2) {
                float2 bb = *(const float2*)&bias[c];
                v0 += bb.x; v1 += bb.y; v2 += bb.x; v3 += bb.y;
            }
            if (EPI == 2) {
                __half* C = (__half*)Cv;
                __half2 o0, o1;
                o0.x = __float2half_rn(gelu_erf(v0)); o0.y = __float2half_rn(gelu_erf(v1));
                o1.x = __float2half_rn(gelu_erf(v2)); o1.y = __float2half_rn(gelu_erf(v3));
                *(__half2*)&C[(size_t)r0 * N + c] = o0;
                *(__half2*)&C[(size_t)(r0 + 8) * N + c] = o1;
            } else {
                float* C = (float*)Cv;
                if (EPI == 3) {
                    float2 ra = *(const float2*)&res[(size_t)r0 * N + c];
                    float2 rb = *(const float2*)&res[(size_t)(r0 + 8) * N + c];
                    v0 += ra.x; v1 += ra.y; v2 += rb.x; v3 += rb.y;
                }
                float2 o0; o0.x = v0; o0.y = v1;
                float2 o1; o1.x = v2; o1.y = v3;
                *(float2*)&C[(size_t)r0 * N + c] = o0;
                *(float2*)&C[(size_t)(r0 + 8) * N + c] = o1;
            }
        }
    }
}

// ---------------- fp16 GEMM, BM=64 (wave-tail variant for MLP2) ----------------
// 64x128x32 tile, 8 warps as 2m x 4n (warp tile 32x32), same stride-40 layout.
#define H64_ASZ (64 * H_SH)
#define H64_STG (H64_ASZ + 128 * H_SH)
#define H64_SMEM_BYTES (H_NSTAGE * H64_STG * 2)

template<int EPI>
__global__ __launch_bounds__(256, 2) void hgemm64(
    const __half* __restrict__ A, const __half* __restrict__ Bt,
    const float* __restrict__ bias, const float* __restrict__ res,
    void* __restrict__ Cv, int M, int N, int K)
{
    extern __shared__ __half smh[];
    unsigned sbase = (unsigned)__cvta_generic_to_shared(smh);

    int tid = threadIdx.x;
    int row0 = blockIdx.y * 64, col0 = blockIdx.x * 128;
    int warp = tid >> 5, lane = tid & 31;
    int wm = (warp & 1) * 32, wn = (warp >> 1) * 32;
    int gid = lane >> 2, tig = lane & 3;
    int within = lane & 7, sub = lane >> 3;

    int ar = tid >> 2, ac = tid & 3;
    int br = tid >> 1, bc0 = (tid & 1) * 2;

    const __half* Ag = A + (size_t)(row0 + ar) * K;
    const __half* Bg = Bt + (size_t)(col0 + br) * K;
    bool bok = (col0 + br) < N;

    float acc[2][4][4];
    #pragma unroll
    for (int t = 0; t < 2; ++t)
        #pragma unroll
        for (int u = 0; u < 4; ++u)
            #pragma unroll
            for (int v = 0; v < 4; ++v) acc[t][u][v] = 0.f;

    int KT = K >> 5;

    auto issue = [&](int kt) {
        int stg = kt & (H_NSTAGE - 1);
        int koff = kt * 32;
        unsigned abase = sbase + (stg * H64_STG) * 2;
        unsigned bbase = abase + H64_ASZ * 2;
        cp16(abase + (ar * H_SH + ac * 8) * 2, Ag + koff + ac * 8, 16);
        #pragma unroll
        for (int s = 0; s < 2; ++s) {
            int c = bc0 + s;
            cp16(bbase + (br * H_SH + c * 8) * 2, Bg + koff + c * 8, bok ? 16 : 0);
        }
        cp_commit();
    };

    issue(0);
    if (KT > 1) issue(1);
    if (KT > 2) issue(2);

    int a_off = (wm + (sub & 1) * 8 + within) * H_SH + (sub >> 1) * 8;
    int b_off = (wn + (sub >> 1) * 8 + within) * H_SH + (sub & 1) * 8;

    for (int kt = 0; kt < KT; ++kt) {
        if (kt + 2 <= KT - 1) cp_wait<2>(); else cp_wait<0>();
        __syncthreads();
        if (kt + 3 < KT) issue(kt + 3);

        unsigned abase = sbase + ((kt & (H_NSTAGE - 1)) * H64_STG) * 2;
        unsigned bbase = abase + H64_ASZ * 2;

        #pragma unroll
        for (int ks = 0; ks < 2; ++ks) {
            int kb = ks * 16;
            unsigned aR[2][4], bR[2][4];
            #pragma unroll
            for (int t = 0; t < 2; ++t)
                ldm4(aR[t], abase + (a_off + t * 16 * H_SH + kb) * 2);
            #pragma unroll
            for (int u = 0; u < 2; ++u)
                ldm4(bR[u], bbase + (b_off + u * 16 * H_SH + kb) * 2);
            #pragma unroll
            for (int t = 0; t < 2; ++t)
                #pragma unroll
                for (int u8 = 0; u8 < 4; ++u8) {
                    int u4 = u8 >> 1, hi = u8 & 1;
                    mma16816(acc[t][u8], aR[t], bR[u4][hi * 2], bR[u4][hi * 2 + 1]);
                }
        }
    }

    #pragma unroll
    for (int t = 0; t < 2; ++t) {
        #pragma unroll
        for (int u = 0; u < 4; ++u) {
            int c = col0 + wn + u * 8 + tig * 2;
            if (c >= N) continue;
            int r0 = row0 + wm + t * 16 + gid;
            float v0 = acc[t][u][0], v1 = acc[t][u][1];
            float v2 = acc[t][u][2], v3 = acc[t][u][3];
            float* C = (float*)Cv;
            if (EPI == 3) {
                float2 bb = *(const float2*)&bias[c];
                float2 ra = *(const float2*)&res[(size_t)r0 * N + c];
                float2 rb = *(const float2*)&res[(size_t)(r0 + 8) * N + c];
                v0 += bb.x + ra.x; v1 += bb.y + ra.y;
                v2 += bb.x + rb.x; v3 += bb.y + rb.y;
            }
            float2 o0; o0.x = v0; o0.y = v1;
            float2 o1; o1.x = v2; o1.y = v3;
            *(float2*)&C[(size_t)r0 * N + c] = o0;
            *(float2*)&C[(size_t)(r0 + 8) * N + c] = o1;
        }
    }
}

// ---------------- Flash attention on mma.sync (shift-free softmax) ----------------
#define AQ_STRIDE 24
#define AV_STRIDE 1032
#define ATT_QS_H (256 * AQ_STRIDE)
#define ATT_KS_H (1024 * AQ_STRIDE)
#define ATT_VT_H (16 * AV_STRIDE)
#define ATT_SMEM ((ATT_QS_H + ATT_KS_H + ATT_VT_H) * 2)

__global__ __launch_bounds__(256, 2) void attn_kernel(const float* __restrict__ qkv,
                                                      __half* __restrict__ out)
{
    extern __shared__ __half asm_[];
    __half* Qs = asm_;
    __half* Ks = Qs + ATT_QS_H;
    __half* Vt = Ks + ATT_KS_H;
    unsigned qs_a = (unsigned)__cvta_generic_to_shared(Qs);
    unsigned ks_a = (unsigned)__cvta_generic_to_shared(Ks);
    unsigned vt_a = (unsigned)__cvta_generic_to_shared(Vt);

    int chunk = blockIdx.x, h = blockIdx.y, b = blockIdx.z;
    int tid = threadIdx.x;
    const float scale = 0.10206207261596575f;  // 96^-0.5

    {
        int qrow = tid;
        const float* qp = qkv + (size_t)(b * NN + chunk * 256 + qrow) * (3 * INNERD) + h * HEAD_D;
        float4 q0 = *(const float4*)(qp);
        float4 q1 = *(const float4*)(qp + 4);
        float4 q2 = *(const float4*)(qp + 8);
        __half2* d = (__half2*)(Qs + qrow * AQ_STRIDE);
        d[0] = __floats2half2_rn(q0.x * scale, q0.y * scale);
        d[1] = __floats2half2_rn(q0.z * scale, q0.w * scale);
        d[2] = __floats2half2_rn(q1.x * scale, q1.y * scale);
        d[3] = __floats2half2_rn(q1.z * scale, q1.w * scale);
        d[4] = __floats2half2_rn(q2.x * scale, q2.y * scale);
        d[5] = __floats2half2_rn(q2.z * scale, q2.w * scale);
        d[6] = __floats2half2_rn(0.f, 0.f);
        d[7] = __floats2half2_rn(0.f, 0.f);
    }
    #pragma unroll
    for (int r = 0; r < 4; ++r) {
        int key = r * 256 + tid;
        const float* base = qkv + (size_t)(b * NN + key) * (3 * INNERD);
        const float* kp = base + INNERD + h * HEAD_D;
        const float* vp = base + 2 * INNERD + h * HEAD_D;
        float4 k0 = *(const float4*)(kp);
        float4 k1 = *(const float4*)(kp + 4);
        float4 k2 = *(const float4*)(kp + 8);
        __half2* d = (__half2*)(Ks + key * AQ_STRIDE);
        d[0] = __floats2half2_rn(k0.x, k0.y);
        d[1] = __floats2half2_rn(k0.z, k0.w);
        d[2] = __floats2half2_rn(k1.x, k1.y);
        d[3] = __floats2half2_rn(k1.z, k1.w);
        d[4] = __floats2half2_rn(k2.x, k2.y);
        d[5] = __floats2half2_rn(k2.z, k2.w);
        d[6] = __floats2half2_rn(0.f, 0.f);
        d[7] = __floats2half2_rn(0.f, 0.f);
        float4 v0 = *(const float4*)(vp);
        float4 v1 = *(const float4*)(vp + 4);
        float4 v2 = *(const float4*)(vp + 8);
        float vv[12] = {v0.x,v0.y,v0.z,v0.w, v1.x,v1.y,v1.z,v1.w, v2.x,v2.y,v2.z,v2.w};
        #pragma unroll
        for (int dd = 0; dd < 12; ++dd)
            Vt[dd * AV_STRIDE + key] = __float2half_rn(vv[dd]);
    }
    for (int idx = tid; idx < 2 * AV_STRIDE; idx += 256)
        *(__half2*)(Vt + 12 * AV_STRIDE + idx * 2) = __floats2half2_rn(0.f, 0.f);
    __syncthreads();

    int warp = tid >> 5, lane = tid & 31;
    int gid = lane >> 2, tig = lane & 3;
    int within = lane & 7, sub = lane >> 3;
    int wm = warp * 32;

    unsigned aQ[2][4];
    {
        int a_off = (wm + (sub & 1) * 8 + within) * AQ_STRIDE + (sub >> 1) * 8;
        ldm4(aQ[0], qs_a + a_off * 2);
        ldm4(aQ[1], qs_a + (a_off + 16 * AQ_STRIDE) * 2);
    }
    int bk_off = ((sub >> 1) * 8 + within) * AQ_STRIDE + (sub & 1) * 8;
    int bv_off = ((sub >> 1) * 8 + within) * AV_STRIDE + (sub & 1) * 8;

    float O[2][2][4];
    #pragma unroll
    for (int mt = 0; mt < 2; ++mt)
        #pragma unroll
        for (int nt = 0; nt < 2; ++nt)
            #pragma unroll
            for (int v = 0; v < 4; ++v) O[mt][nt][v] = 0.f;
    float rs[4] = {0.f, 0.f, 0.f, 0.f};

    for (int kb = 0; kb < NN / 16; ++kb) {
        unsigned bK[4], bV[4];
        ldm4(bK, ks_a + (bk_off + kb * 16 * AQ_STRIDE) * 2);
        ldm4(bV, vt_a + (bv_off + kb * 16) * 2);

        float S[2][2][4];
        #pragma unroll
        for (int mt = 0; mt < 2; ++mt)
            #pragma unroll
            for (int nt = 0; nt < 2; ++nt) {
                S[mt][nt][0] = S[mt][nt][1] = S[mt][nt][2] = S[mt][nt][3] = 0.f;
                mma16816(S[mt][nt], aQ[mt], bK[nt * 2], bK[nt * 2 + 1]);
            }

        #pragma unroll
        for (int mt = 0; mt < 2; ++mt) {
            unsigned aP[4];
            float e00 = __expf(S[mt][0][0]), e01 = __expf(S[mt][0][1]);
            float e02 = __expf(S[mt][0][2]), e03 = __expf(S[mt][0][3]);
            float e10 = __expf(S[mt][1][0]), e11 = __expf(S[mt][1][1]);
            float e12 = __expf(S[mt][1][2]), e13 = __expf(S[mt][1][3]);
            rs[mt * 2 + 0] += (e00 + e01) + (e10 + e11);
            rs[mt * 2 + 1] += (e02 + e03) + (e12 + e13);
            __half2 p0 = __floats2half2_rn(e00, e01);
            __half2 p1 = __floats2half2_rn(e02, e03);
            __half2 p2 = __floats2half2_rn(e10, e11);
            __half2 p3 = __floats2half2_rn(e12, e13);
            aP[0] = *(unsigned*)&p0;
            aP[1] = *(unsigned*)&p1;
            aP[2] = *(unsigned*)&p2;
            aP[3] = *(unsigned*)&p3;
            mma16816(O[mt][0], aP, bV[0], bV[1]);
            mma16816(O[mt][1], aP, bV[2], bV[3]);
        }
    }

    #pragma unroll
    for (int i = 0; i < 4; ++i) {
        rs[i] += __shfl_xor_sync(0xFFFFFFFFu, rs[i], 1);
        rs[i] += __shfl_xor_sync(0xFFFFFFFFu, rs[i], 2);
    }
    float inv0 = 1.f / rs[0], inv1 = 1.f / rs[1];
    float inv2 = 1.f / rs[2], inv3 = 1.f / rs[3];

    #pragma unroll
    for (int mt = 0; mt < 2; ++mt) {
        float ia = mt ? inv2 : inv0;
        float ib = mt ? inv3 : inv1;
        int r0 = chunk * 256 + wm + mt * 16 + gid;
        __half* oa = out + (size_t)(b * NN + r0) * INNERD + h * HEAD_D;
        __half* ob = out + (size_t)(b * NN + r0 + 8) * INNERD + h * HEAD_D;
        int d0 = 2 * tig;
        *(__half2*)(oa + d0) = __floats2half2_rn(O[mt][0][0] * ia, O[mt][0][1] * ia);
        *(__half2*)(ob + d0) = __floats2half2_rn(O[mt][0][2] * ib, O[mt][0][3] * ib);
        if (tig < 2) {
            int d1 = 8 + 2 * tig;
            *(__half2*)(oa + d1) = __floats2half2_rn(O[mt][1][0] * ia, O[mt][1][1] * ia);
            *(__half2*)(ob + d1) = __floats2half2_rn(O[mt][1][2] * ib, O[mt][1][3] * ib);
        }
    }
}

// ---------------- launch ----------------
extern "C" void kernel_launch(void* const* d_in, const int* in_sizes, int n_in,
                              void* d_out, int out_size)
{
    const float* x     = (const float*)d_in[0];
    const float* ln1g  = (const float*)d_in[3];
    const float* ln1b  = (const float*)d_in[4];
    const float* wqkv  = (const float*)d_in[5];
    const float* wproj = (const float*)d_in[6];
    const float* bproj = (const float*)d_in[7];
    const float* ln2g  = (const float*)d_in[8];
    const float* ln2b  = (const float*)d_in[9];
    const float* w1    = (const float*)d_in[10];
    const float* b1    = (const float*)d_in[11];
    const float* w2    = (const float*)d_in[12];
    const float* b2    = (const float*)d_in[13];
    float* out = (float*)d_out;

    __half *h16, *att16, *mlp16, *wqkv_t, *wproj_t, *w1_t, *w2_t;
    float *qkv, *x1;
    cudaGetSymbolAddress((void**)&h16,    g_h16);
    cudaGetSymbolAddress((void**)&qkv,    g_qkv);
    cudaGetSymbolAddress((void**)&att16,  g_att16);
    cudaGetSymbolAddress((void**)&x1,     g_x1);
    cudaGetSymbolAddress((void**)&mlp16,  g_mlp16);
    cudaGetSymbolAddress((void**)&wqkv_t, g_wqkv_t);
    cudaGetSymbolAddress((void**)&wproj_t,g_wproj_t);
    cudaGetSymbolAddress((void**)&w1_t,   g_w1_t);
    cudaGetSymbolAddress((void**)&w2_t,   g_w2_t);

    cudaFuncSetAttribute(hgemm<0>, cudaFuncAttributeMaxDynamicSharedMemorySize, H_SMEM_BYTES);
    cudaFuncSetAttribute(hgemm<2>, cudaFuncAttributeMaxDynamicSharedMemorySize, H_SMEM_BYTES);
    cudaFuncSetAttribute(hgemm<3>, cudaFuncAttributeMaxDynamicSharedMemorySize, H_SMEM_BYTES);
    cudaFuncSetAttribute(hgemm64<3>, cudaFuncAttributeMaxDynamicSharedMemorySize, H64_SMEM_BYTES);
    cudaFuncSetAttribute(attn_kernel, cudaFuncAttributeMaxDynamicSharedMemorySize, ATT_SMEM);

    cudaStream_t cap = 0;

    static cudaStream_t s2 = nullptr;
    static cudaEvent_t evFork = nullptr, evJoin = nullptr;
    if (!s2) {
        cudaStreamCreateWithFlags(&s2, cudaStreamNonBlocking);
        cudaEventCreateWithFlags(&evFork, cudaEventDisableTiming);
        cudaEventCreateWithFlags(&evJoin, cudaEventDisableTiming);
    }

    cudaEventRecord(evFork, cap);
    cudaStreamWaitEvent(s2, evFork, 0);
    wconv_all<<<4896, 256, 0, s2>>>(wqkv, wqkv_t, wproj, wproj_t, w1, w1_t, w2, w2_t);
    cudaEventRecord(evJoin, s2);

    // 1) LN1 -> h16 (parallel with wconv_all)
    ln_kernel<<<ROWS, 256, 0, cap>>>(x, ln1g, ln1b, h16);

    cudaStreamWaitEvent(cap, evJoin, 0);

    // 2) QKV GEMM: [8192,768] x [768,288] -> fp32 qkv
    hgemm<0><<<dim3(3, ROWS / 128), 256, H_SMEM_BYTES, cap>>>(
        h16, wqkv_t, nullptr, nullptr, qkv, ROWS, 3 * INNERD, EMBD);

    // 3) flash attention (mma) -> att16
    attn_kernel<<<dim3(NN / 256, HEADS, BB), 256, ATT_SMEM, cap>>>(qkv, att16);

    // 4) proj GEMM + bias + residual(x) -> x1 fp32
    hgemm<3><<<dim3(EMBD / 128, ROWS / 128), 256, H_SMEM_BYTES, cap>>>(
        att16, wproj_t, bproj, x, x1, ROWS, EMBD, INNERD);

    // 5) LN2 -> h16
    ln_kernel<<<ROWS, 256, 0, cap>>>(x1, ln2g, ln2b, h16);

    // 6) MLP1 + bias + exact gelu -> mlp16
    hgemm<2><<<dim3(MLP_D / 128, ROWS / 128), 256, H_SMEM_BYTES, cap>>>(
        h16, w1_t, b1, nullptr, mlp16, ROWS, MLP_D, EMBD);

    // 7) MLP2 (BM=64, better wave fill) + bias + residual(x1) -> d_out fp32
    hgemm64<3><<<dim3(EMBD / 128, ROWS / 64), 256, H64_SMEM_BYTES, cap>>>(
        mlp16, w2_t, b2, x1, out, ROWS, EMBD, MLP_D);
}

// round 15
// speedup vs baseline: 1.1090x; 1.1090x over previous
#include <cuda_runtime.h>
#include <cuda_fp16.h>
#include <math.h>

#define BB 8
#define NN 1024
#define EMBD 768
#define HEADS 8
#define INNERD 96
#define HEAD_D 12
#define MLP_D 3072
#define ROWS (BB*NN)   // 8192

// ---------------- scratch (no allocations allowed) ----------------
__device__ __half g_h16[ROWS * EMBD];
__device__ float  g_qkv[ROWS * 3 * INNERD];
__device__ __half g_att16[ROWS * INNERD];
__device__ float  g_x1[ROWS * EMBD];
__device__ __half g_mlp16[ROWS * MLP_D];
__device__ __half g_wqkv_t[3 * INNERD * EMBD];
__device__ __half g_wproj_t[EMBD * INNERD];
__device__ __half g_w1_t[MLP_D * EMBD];
__device__ __half g_w2_t[EMBD * MLP_D];

// ---------------- merged weight transpose + fp32->fp16 convert ----------------
__global__ __launch_bounds__(256) void wconv_all(
    const float* s0, __half* d0,
    const float* s1, __half* d1,
    const float* s2, __half* d2,
    const float* s3, __half* d3)
{
    int bid = blockIdx.x;
    const float* src; __half* dst; int K, N, ntx, t;
    if (bid < 216)       { src = s0; dst = d0; K = EMBD;  N = 3*INNERD; ntx = 9;  t = bid; }
    else if (bid < 288)  { src = s1; dst = d1; K = INNERD; N = EMBD;    ntx = 24; t = bid - 216; }
    else if (bid < 2592) { src = s2; dst = d2; K = EMBD;  N = MLP_D;    ntx = 96; t = bid - 288; }
    else                 { src = s3; dst = d3; K = MLP_D; N = EMBD;     ntx = 24; t = bid - 2592; }
    int n0 = (t % ntx) * 32, k0 = (t / ntx) * 32;

    __shared__ float sm[32][33];
    int tx = threadIdx.x & 31, ty = threadIdx.x >> 5;
    #pragma unroll
    for (int i = 0; i < 4; ++i)
        sm[ty + i * 8][tx] = src[(size_t)(k0 + ty + i * 8) * N + n0 + tx];
    __syncthreads();
    #pragma unroll
    for (int i = 0; i < 4; ++i)
        dst[(size_t)(n0 + ty + i * 8) * K + k0 + tx] = __float2half_rn(sm[tx][ty + i * 8]);
}

// ---------------- LayerNorm: one warp per row, shfl-only reduction ----------------
__global__ __launch_bounds__(256) void ln_kernel(const float* __restrict__ x,
                                                 const float* __restrict__ g,
                                                 const float* __restrict__ b,
                                                 __half* __restrict__ out)
{
    int warp = threadIdx.x >> 5, lane = threadIdx.x & 31;
    int row = blockIdx.x * 8 + warp;
    const float* xr = x + (size_t)row * EMBD;

    float4 v[6];
    float s1 = 0.f, s2 = 0.f;
    #pragma unroll
    for (int i = 0; i < 6; ++i) {
        v[i] = *(const float4*)&xr[lane * 4 + i * 128];
        s1 += v[i].x + v[i].y + v[i].z + v[i].w;
        s2 += v[i].x*v[i].x + v[i].y*v[i].y + v[i].z*v[i].z + v[i].w*v[i].w;
    }
    #pragma unroll
    for (int o = 16; o > 0; o >>= 1) {
        s1 += __shfl_xor_sync(0xFFFFFFFFu, s1, o);
        s2 += __shfl_xor_sync(0xFFFFFFFFu, s2, o);
    }
    float mu = s1 * (1.f / EMBD);
    float var = s2 * (1.f / EMBD) - mu * mu;
    float rs = rsqrtf(var + 1e-5f);

    __half* orow = out + (size_t)row * EMBD;
    #pragma unroll
    for (int i = 0; i < 6; ++i) {
        int c = lane * 4 + i * 128;
        float4 gg = *(const float4*)&g[c];
        float4 bb = *(const float4*)&b[c];
        __half2 o0, o1;
        o0.x = __float2half_rn((v[i].x - mu) * rs * gg.x + bb.x);
        o0.y = __float2half_rn((v[i].y - mu) * rs * gg.y + bb.y);
        o1.x = __float2half_rn((v[i].z - mu) * rs * gg.z + bb.z);
        o1.y = __float2half_rn((v[i].w - mu) * rs * gg.w + bb.w);
        *(__half2*)&orow[c] = o0;
        *(__half2*)&orow[c + 2] = o1;
    }
}

// ---------------- common mma helpers ----------------
__device__ __forceinline__ float gelu_erf(float v) {
    return 0.5f * v * (1.f + erff(v * 0.70710678118654752f));
}
__device__ __forceinline__ void cp16(unsigned dst, const void* src, int srcBytes) {
    asm volatile("cp.async.cg.shared.global [%0], [%1], 16, %2;"
                 :: "r"(dst), "l"(src), "r"(srcBytes));
}
__device__ __forceinline__ void cp_commit() {
    asm volatile("cp.async.commit_group;");
}
template<int Nw>
__device__ __forceinline__ void cp_wait() {
    asm volatile("cp.async.wait_group %0;" :: "n"(Nw));
}
__device__ __forceinline__ void ldm4(unsigned* r, unsigned addr) {
    asm volatile("ldmatrix.sync.aligned.m8n8.x4.shared.b16 {%0,%1,%2,%3}, [%4];"
                 : "=r"(r[0]), "=r"(r[1]), "=r"(r[2]), "=r"(r[3]) : "r"(addr));
}
__device__ __forceinline__ void mma16816(float* c, const unsigned* a, unsigned b0, unsigned b1) {
    asm volatile(
        "mma.sync.aligned.m16n8k16.row.col.f32.f16.f16.f32 "
        "{%0,%1,%2,%3}, {%4,%5,%6,%7}, {%8,%9}, {%0,%1,%2,%3};"
        : "+f"(c[0]), "+f"(c[1]), "+f"(c[2]), "+f"(c[3])
        : "r"(a[0]), "r"(a[1]), "r"(a[2]), "r"(a[3]), "r"(b0), "r"(b1));
}

// ---------------- fp16 tensor-core GEMM, BM=128, 4-stage cp.async ----------------
#define H_SH 40
#define H_TILE (128 * H_SH)
#define H_STG (2 * H_TILE)
#define H_NSTAGE 4
#define H_SMEM_BYTES (H_NSTAGE * H_STG * 2)

// EPI: 0 = fp32 C; 2 = +bias, exact gelu, fp16 C; 3 = +bias +fp32 residual, fp32 C.
template<int EPI>
__global__ __launch_bounds__(256, 2) void hgemm(
    const __half* __restrict__ A, const __half* __restrict__ Bt,
    const float* __restrict__ bias, const float* __restrict__ res,
    void* __restrict__ Cv, int M, int N, int K)
{
    extern __shared__ __half smh[];
    unsigned sbase = (unsigned)__cvta_generic_to_shared(smh);

    int tid = threadIdx.x;
    int row0 = blockIdx.y * 128, col0 = blockIdx.x * 128;
    int warp = tid >> 5, lane = tid & 31;
    int wm = (warp & 3) * 32, wn = (warp >> 2) * 64;
    int gid = lane >> 2, tig = lane & 3;
    int within = lane & 7, sub = lane >> 3;

    int lr = tid >> 1;
    int lc0 = (tid & 1) * 2;

    const __half* Ag = A + (size_t)(row0 + lr) * K;
    const __half* Bg = Bt + (size_t)(col0 + lr) * K;
    bool bok = (col0 + lr) < N;

    float acc[2][8][4];
    #pragma unroll
    for (int t = 0; t < 2; ++t)
        #pragma unroll
        for (int u = 0; u < 8; ++u)
            #pragma unroll
            for (int v = 0; v < 4; ++v) acc[t][u][v] = 0.f;

    int KT = K >> 5;

    auto issue = [&](int kt) {
        int stg = kt & (H_NSTAGE - 1);
        int koff = kt * 32;
        unsigned abase = sbase + (stg * H_STG) * 2;
        unsigned bbase = abase + H_TILE * 2;
        #pragma unroll
        for (int s = 0; s < 2; ++s) {
            int c = lc0 + s;
            cp16(abase + (lr * H_SH + c * 8) * 2, Ag + koff + c * 8, 16);
            cp16(bbase + (lr * H_SH + c * 8) * 2, Bg + koff + c * 8, bok ? 16 : 0);
        }
        cp_commit();
    };

    issue(0);
    if (KT > 1) issue(1);
    if (KT > 2) issue(2);

    int a_off = (wm + (sub & 1) * 8 + within) * H_SH + (sub >> 1) * 8;
    int b_off = (wn + (sub >> 1) * 8 + within) * H_SH + (sub & 1) * 8;

    for (int kt = 0; kt < KT; ++kt) {
        if (kt + 2 <= KT - 1) cp_wait<2>(); else cp_wait<0>();
        __syncthreads();
        if (kt + 3 < KT) issue(kt + 3);

        unsigned abase = sbase + ((kt & (H_NSTAGE - 1)) * H_STG) * 2;
        unsigned bbase = abase + H_TILE * 2;

        #pragma unroll
        for (int ks = 0; ks < 2; ++ks) {
            int kb = ks * 16;
            unsigned aR[2][4], bR[4][4];
            #pragma unroll
            for (int t = 0; t < 2; ++t)
                ldm4(aR[t], abase + (a_off + t * 16 * H_SH + kb) * 2);
            #pragma unroll
            for (int u = 0; u < 4; ++u)
                ldm4(bR[u], bbase + (b_off + u * 16 * H_SH + kb) * 2);
            #pragma unroll
            for (int t = 0; t < 2; ++t)
                #pragma unroll
                for (int u8 = 0; u8 < 8; ++u8) {
                    int u4 = u8 >> 1, hi = u8 & 1;
                    mma16816(acc[t][u8], aR[t], bR[u4][hi * 2], bR[u4][hi * 2 + 1]);
                }
        }
    }

    #pragma unroll
    for (int t = 0; t < 2; ++t) {
        #pragma unroll
        for (int u = 0; u < 8; ++u) {
            int c = col0 + wn + u * 8 + tig * 2;
            if (c >= N) continue;
            int r0 = row0 + wm + t * 16 + gid;
            float v0 = acc[t][u][0], v1 = acc[t][u][1];
            float v2 = acc[t][u][2], v3 = acc[t][u][3];
            if (EPI >= 2) {
                float2 bb = *(const float2*)&bias[c];
                v0 += bb.x; v1 += bb.y; v2 += bb.x; v3 += bb.y;
            }
            if (EPI == 2) {
                __half* C = (__half*)Cv;
                __half2 o0, o1;
                o0.x = __float2half_rn(gelu_erf(v0)); o0.y = __float2half_rn(gelu_erf(v1));
                o1.x = __float2half_rn(gelu_erf(v2)); o1.y = __float2half_rn(gelu_erf(v3));
                *(__half2*)&C[(size_t)r0 * N + c] = o0;
                *(__half2*)&C[(size_t)(r0 + 8) * N + c] = o1;
            } else {
                float* C = (float*)Cv;
                if (EPI == 3) {
                    float2 ra = *(const float2*)&res[(size_t)r0 * N + c];
                    float2 rb = *(const float2*)&res[(size_t)(r0 + 8) * N + c];
                    v0 += ra.x; v1 += ra.y; v2 += rb.x; v3 += rb.y;
                }
                float2 o0; o0.x = v0; o0.y = v1;
                float2 o1; o1.x = v2; o1.y = v3;
                *(float2*)&C[(size_t)r0 * N + c] = o0;
                *(float2*)&C[(size_t)(r0 + 8) * N + c] = o1;
            }
        }
    }
}

// ---------------- Flash attention on mma.sync (shift-free softmax) ----------------
#define AQ_STRIDE 24
#define AV_STRIDE 1032
#define ATT_QS_H (256 * AQ_STRIDE)
#define ATT_KS_H (1024 * AQ_STRIDE)
#define ATT_VT_H (16 * AV_STRIDE)
#define ATT_SMEM ((ATT_QS_H + ATT_KS_H + ATT_VT_H) * 2)

__global__ __launch_bounds__(256, 2) void attn_kernel(const float* __restrict__ qkv,
                                                      __half* __restrict__ out)
{
    extern __shared__ __half asm_[];
    __half* Qs = asm_;
    __half* Ks = Qs + ATT_QS_H;
    __half* Vt = Ks + ATT_KS_H;
    unsigned qs_a = (unsigned)__cvta_generic_to_shared(Qs);
    unsigned ks_a = (unsigned)__cvta_generic_to_shared(Ks);
    unsigned vt_a = (unsigned)__cvta_generic_to_shared(Vt);

    int chunk = blockIdx.x, h = blockIdx.y, b = blockIdx.z;
    int tid = threadIdx.x;
    const float scale = 0.10206207261596575f;  // 96^-0.5

    {
        int qrow = tid;
        const float* qp = qkv + (size_t)(b * NN + chunk * 256 + qrow) * (3 * INNERD) + h * HEAD_D;
        float4 q0 = *(const float4*)(qp);
        float4 q1 = *(const float4*)(qp + 4);
        float4 q2 = *(const float4*)(qp + 8);
        __half2* d = (__half2*)(Qs + qrow * AQ_STRIDE);
        d[0] = __floats2half2_rn(q0.x * scale, q0.y * scale);
        d[1] = __floats2half2_rn(q0.z * scale, q0.w * scale);
        d[2] = __floats2half2_rn(q1.x * scale, q1.y * scale);
        d[3] = __floats2half2_rn(q1.z * scale, q1.w * scale);
        d[4] = __floats2half2_rn(q2.x * scale, q2.y * scale);
        d[5] = __floats2half2_rn(q2.z * scale, q2.w * scale);
        d[6] = __floats2half2_rn(0.f, 0.f);
        d[7] = __floats2half2_rn(0.f, 0.f);
    }
    #pragma unroll
    for (int r = 0; r < 4; ++r) {
        int key = r * 256 + tid;
        const float* base = qkv + (size_t)(b * NN + key) * (3 * INNERD);
        const float* kp = base + INNERD + h * HEAD_D;
        const float* vp = base + 2 * INNERD + h * HEAD_D;
        float4 k0 = *(const float4*)(kp);
        float4 k1 = *(const float4*)(kp + 4);
        float4 k2 = *(const float4*)(kp + 8);
        __half2* d = (__half2*)(Ks + key * AQ_STRIDE);
        d[0] = __floats2half2_rn(k0.x, k0.y);
        d[1] = __floats2half2_rn(k0.z, k0.w);
        d[2] = __floats2half2_rn(k1.x, k1.y);
        d[3] = __floats2half2_rn(k1.z, k1.w);
        d[4] = __floats2half2_rn(k2.x, k2.y);
        d[5] = __floats2half2_rn(k2.z, k2.w);
        d[6] = __floats2half2_rn(0.f, 0.f);
        d[7] = __floats2half2_rn(0.f, 0.f);
        float4 v0 = *(const float4*)(vp);
        float4 v1 = *(const float4*)(vp + 4);
        float4 v2 = *(const float4*)(vp + 8);
        float vv[12] = {v0.x,v0.y,v0.z,v0.w, v1.x,v1.y,v1.z,v1.w, v2.x,v2.y,v2.z,v2.w};
        #pragma unroll
        for (int dd = 0; dd < 12; ++dd)
            Vt[dd * AV_STRIDE + key] = __float2half_rn(vv[dd]);
    }
    for (int idx = tid; idx < 2 * AV_STRIDE; idx += 256)
        *(__half2*)(Vt + 12 * AV_STRIDE + idx * 2) = __floats2half2_rn(0.f, 0.f);
    __syncthreads();

    int warp = tid >> 5, lane = tid & 31;
    int gid = lane >> 2, tig = lane & 3;
    int within = lane & 7, sub = lane >> 3;
    int wm = warp * 32;

    unsigned aQ[2][4];
    {
        int a_off = (wm + (sub & 1) * 8 + within) * AQ_STRIDE + (sub >> 1) * 8;
        ldm4(aQ[0], qs_a + a_off * 2);
        ldm4(aQ[1], qs_a + (a_off + 16 * AQ_STRIDE) * 2);
    }
    int bk_off = ((sub >> 1) * 8 + within) * AQ_STRIDE + (sub & 1) * 8;
    int bv_off = ((sub >> 1) * 8 + within) * AV_STRIDE + (sub & 1) * 8;

    float O[2][2][4];
    #pragma unroll
    for (int mt = 0; mt < 2; ++mt)
        #pragma unroll
        for (int nt = 0; nt < 2; ++nt)
            #pragma unroll
            for (int v = 0; v < 4; ++v) O[mt][nt][v] = 0.f;
    float rs[4] = {0.f, 0.f, 0.f, 0.f};

    for (int kb = 0; kb < NN / 16; ++kb) {
        unsigned bK[4], bV[4];
        ldm4(bK, ks_a + (bk_off + kb * 16 * AQ_STRIDE) * 2);
        ldm4(bV, vt_a + (bv_off + kb * 16) * 2);

        float S[2][2][4];
        #pragma unroll
        for (int mt = 0; mt < 2; ++mt)
            #pragma unroll
            for (int nt = 0; nt < 2; ++nt) {
                S[mt][nt][0] = S[mt][nt][1] = S[mt][nt][2] = S[mt][nt][3] = 0.f;
                mma16816(S[mt][nt], aQ[mt], bK[nt * 2], bK[nt * 2 + 1]);
            }

        #pragma unroll
        for (int mt = 0; mt < 2; ++mt) {
            unsigned aP[4];
            float e00 = __expf(S[mt][0][0]), e01 = __expf(S[mt][0][1]);
            float e02 = __expf(S[mt][0][2]), e03 = __expf(S[mt][0][3]);
            float e10 = __expf(S[mt][1][0]), e11 = __expf(S[mt][1][1]);
            float e12 = __expf(S[mt][1][2]), e13 = __expf(S[mt][1][3]);
            rs[mt * 2 + 0] += (e00 + e01) + (e10 + e11);
            rs[mt * 2 + 1] += (e02 + e03) + (e12 + e13);
            __half2 p0 = __floats2half2_rn(e00, e01);
            __half2 p1 = __floats2half2_rn(e02, e03);
            __half2 p2 = __floats2half2_rn(e10, e11);
            __half2 p3 = __floats2half2_rn(e12, e13);
            aP[0] = *(unsigned*)&p0;
            aP[1] = *(unsigned*)&p1;
            aP[2] = *(unsigned*)&p2;
            aP[3] = *(unsigned*)&p3;
            mma16816(O[mt][0], aP, bV[0], bV[1]);
            mma16816(O[mt][1], aP, bV[2], bV[3]);
        }
    }

    #pragma unroll
    for (int i = 0; i < 4; ++i) {
        rs[i] += __shfl_xor_sync(0xFFFFFFFFu, rs[i], 1);
        rs[i] += __shfl_xor_sync(0xFFFFFFFFu, rs[i], 2);
    }
    float inv0 = 1.f / rs[0], inv1 = 1.f / rs[1];
    float inv2 = 1.f / rs[2], inv3 = 1.f / rs[3];

    #pragma unroll
    for (int mt = 0; mt < 2; ++mt) {
        float ia = mt ? inv2 : inv0;
        float ib = mt ? inv3 : inv1;
        int r0 = chunk * 256 + wm + mt * 16 + gid;
        __half* oa = out + (size_t)(b * NN + r0) * INNERD + h * HEAD_D;
        __half* ob = out + (size_t)(b * NN + r0 + 8) * INNERD + h * HEAD_D;
        int d0 = 2 * tig;
        *(__half2*)(oa + d0) = __floats2half2_rn(O[mt][0][0] * ia, O[mt][0][1] * ia);
        *(__half2*)(ob + d0) = __floats2half2_rn(O[mt][0][2] * ib, O[mt][0][3] * ib);
        if (tig < 2) {
            int d1 = 8 + 2 * tig;
            *(__half2*)(oa + d1) = __floats2half2_rn(O[mt][1][0] * ia, O[mt][1][1] * ia);
            *(__half2*)(ob + d1) = __floats2half2_rn(O[mt][1][2] * ib, O[mt][1][3] * ib);
        }
    }
}

// ---------------- launch ----------------
extern "C" void kernel_launch(void* const* d_in, const int* in_sizes, int n_in,
                              void* d_out, int out_size)
{
    const float* x     = (const float*)d_in[0];
    const float* ln1g  = (const float*)d_in[3];
    const float* ln1b  = (const float*)d_in[4];
    const float* wqkv  = (const float*)d_in[5];
    const float* wproj = (const float*)d_in[6];
    const float* bproj = (const float*)d_in[7];
    const float* ln2g  = (const float*)d_in[8];
    const float* ln2b  = (const float*)d_in[9];
    const float* w1    = (const float*)d_in[10];
    const float* b1    = (const float*)d_in[11];
    const float* w2    = (const float*)d_in[12];
    const float* b2    = (const float*)d_in[13];
    float* out = (float*)d_out;

    __half *h16, *att16, *mlp16, *wqkv_t, *wproj_t, *w1_t, *w2_t;
    float *qkv, *x1;
    cudaGetSymbolAddress((void**)&h16,    g_h16);
    cudaGetSymbolAddress((void**)&qkv,    g_qkv);
    cudaGetSymbolAddress((void**)&att16,  g_att16);
    cudaGetSymbolAddress((void**)&x1,     g_x1);
    cudaGetSymbolAddress((void**)&mlp16,  g_mlp16);
    cudaGetSymbolAddress((void**)&wqkv_t, g_wqkv_t);
    cudaGetSymbolAddress((void**)&wproj_t,g_wproj_t);
    cudaGetSymbolAddress((void**)&w1_t,   g_w1_t);
    cudaGetSymbolAddress((void**)&w2_t,   g_w2_t);

    cudaFuncSetAttribute(hgemm<0>, cudaFuncAttributeMaxDynamicSharedMemorySize, H_SMEM_BYTES);
    cudaFuncSetAttribute(hgemm<2>, cudaFuncAttributeMaxDynamicSharedMemorySize, H_SMEM_BYTES);
    cudaFuncSetAttribute(hgemm<3>, cudaFuncAttributeMaxDynamicSharedMemorySize, H_SMEM_BYTES);
    cudaFuncSetAttribute(attn_kernel, cudaFuncAttributeMaxDynamicSharedMemorySize, ATT_SMEM);

    cudaStream_t cap = 0;

    static cudaStream_t s2 = nullptr;
    static cudaEvent_t evFork = nullptr, evJoin = nullptr;
    if (!s2) {
        cudaStreamCreateWithFlags(&s2, cudaStreamNonBlocking);
        cudaEventCreateWithFlags(&evFork, cudaEventDisableTiming);
        cudaEventCreateWithFlags(&evJoin, cudaEventDisableTiming);
    }

    cudaEventRecord(evFork, cap);
    cudaStreamWaitEvent(s2, evFork, 0);
    wconv_all<<<4896, 256, 0, s2>>>(wqkv, wqkv_t, wproj, wproj_t, w1, w1_t, w2, w2_t);
    cudaEventRecord(evJoin, s2);

    // 1) LN1 -> h16 (warp-per-row; parallel with wconv_all)
    ln_kernel<<<ROWS / 8, 256, 0, cap>>>(x, ln1g, ln1b, h16);

    cudaStreamWaitEvent(cap, evJoin, 0);

    // 2) QKV GEMM: [8192,768] x [768,288] -> fp32 qkv
    hgemm<0><<<dim3(3, ROWS / 128), 256, H_SMEM_BYTES, cap>>>(
        h16, wqkv_t, nullptr, nullptr, qkv, ROWS, 3 * INNERD, EMBD);

    // 3) flash attention (mma) -> att16
    attn_kernel<<<dim3(NN / 256, HEADS, BB), 256, ATT_SMEM, cap>>>(qkv, att16);

    // 4) proj GEMM + bias + residual(x) -> x1 fp32
    hgemm<3><<<dim3(EMBD / 128, ROWS / 128), 256, H_SMEM_BYTES, cap>>>(
        att16, wproj_t, bproj, x, x1, ROWS, EMBD, INNERD);

    // 5) LN2 -> h16 (warp-per-row)
    ln_kernel<<<ROWS / 8, 256, 0, cap>>>(x1, ln2g, ln2b, h16);

    // 6) MLP1 + bias + exact gelu -> mlp16
    hgemm<2><<<dim3(MLP_D / 128, ROWS / 128), 256, H_SMEM_BYTES, cap>>>(
        h16, w1_t, b1, nullptr, mlp16, ROWS, MLP_D, EMBD);

    // 7) MLP2 (BM=128, proven config) + bias + residual(x1) -> d_out fp32
    hgemm<3><<<dim3(EMBD / 128, ROWS / 128), 256, H_SMEM_BYTES, cap>>>(
        mlp16, w2_t, b2, x1, out, ROWS, EMBD, MLP_D);
}

// round 16
// speedup vs baseline: 1.1133x; 1.0040x over previous
#include <cuda_runtime.h>
#include <cuda_fp16.h>
#include <math.h>

#define BB 8
#define NN 1024
#define EMBD 768
#define HEADS 8
#define INNERD 96
#define HEAD_D 12
#define MLP_D 3072
#define ROWS (BB*NN)   // 8192

// ---------------- scratch (no allocations allowed) ----------------
__device__ __half g_h16[ROWS * EMBD];
__device__ __half g_qkv16[ROWS * 3 * INNERD];   // fp16 qkv (Q pre-scaled)
__device__ __half g_att16[ROWS * INNERD];
__device__ float  g_x1[ROWS * EMBD];
__device__ __half g_mlp16[ROWS * MLP_D];
__device__ __half g_wqkv_t[3 * INNERD * EMBD];
__device__ __half g_wproj_t[EMBD * INNERD];
__device__ __half g_w1_t[MLP_D * EMBD];
__device__ __half g_w2_t[EMBD * MLP_D];

// ---------------- merged weight transpose + fp32->fp16 convert ----------------
// Job 0 (wqkv): rows n < 96 (the Q block) are pre-scaled by 96^-0.5.
__global__ __launch_bounds__(256) void wconv_all(
    const float* s0, __half* d0,
    const float* s1, __half* d1,
    const float* s2, __half* d2,
    const float* s3, __half* d3)
{
    int bid = blockIdx.x;
    const float* src; __half* dst; int K, N, ntx, t;
    bool qscale = false;
    if (bid < 216)       { src = s0; dst = d0; K = EMBD;  N = 3*INNERD; ntx = 9;  t = bid; qscale = true; }
    else if (bid < 288)  { src = s1; dst = d1; K = INNERD; N = EMBD;    ntx = 24; t = bid - 216; }
    else if (bid < 2592) { src = s2; dst = d2; K = EMBD;  N = MLP_D;    ntx = 96; t = bid - 288; }
    else                 { src = s3; dst = d3; K = MLP_D; N = EMBD;     ntx = 24; t = bid - 2592; }
    int n0 = (t % ntx) * 32, k0 = (t / ntx) * 32;

    __shared__ float sm[32][33];
    int tx = threadIdx.x & 31, ty = threadIdx.x >> 5;
    #pragma unroll
    for (int i = 0; i < 4; ++i)
        sm[ty + i * 8][tx] = src[(size_t)(k0 + ty + i * 8) * N + n0 + tx];
    __syncthreads();
    const float qsc = 0.10206207261596575f;  // 96^-0.5
    #pragma unroll
    for (int i = 0; i < 4; ++i) {
        int n = n0 + ty + i * 8;
        float v = sm[tx][ty + i * 8];
        if (qscale && n < INNERD) v *= qsc;
        dst[(size_t)n * K + k0 + tx] = __float2half_rn(v);
    }
}

// ---------------- LayerNorm: one warp per row, shfl-only reduction ----------------
__global__ __launch_bounds__(256) void ln_kernel(const float* __restrict__ x,
                                                 const float* __restrict__ g,
                                                 const float* __restrict__ b,
                                                 __half* __restrict__ out)
{
    int warp = threadIdx.x >> 5, lane = threadIdx.x & 31;
    int row = blockIdx.x * 8 + warp;
    const float* xr = x + (size_t)row * EMBD;

    float4 v[6];
    float s1 = 0.f, s2 = 0.f;
    #pragma unroll
    for (int i = 0; i < 6; ++i) {
        v[i] = *(const float4*)&xr[lane * 4 + i * 128];
        s1 += v[i].x + v[i].y + v[i].z + v[i].w;
        s2 += v[i].x*v[i].x + v[i].y*v[i].y + v[i].z*v[i].z + v[i].w*v[i].w;
    }
    #pragma unroll
    for (int o = 16; o > 0; o >>= 1) {
        s1 += __shfl_xor_sync(0xFFFFFFFFu, s1, o);
        s2 += __shfl_xor_sync(0xFFFFFFFFu, s2, o);
    }
    float mu = s1 * (1.f / EMBD);
    float var = s2 * (1.f / EMBD) - mu * mu;
    float rs = rsqrtf(var + 1e-5f);

    __half* orow = out + (size_t)row * EMBD;
    #pragma unroll
    for (int i = 0; i < 6; ++i) {
        int c = lane * 4 + i * 128;
        float4 gg = *(const float4*)&g[c];
        float4 bb = *(const float4*)&b[c];
        __half2 o0, o1;
        o0.x = __float2half_rn((v[i].x - mu) * rs * gg.x + bb.x);
        o0.y = __float2half_rn((v[i].y - mu) * rs * gg.y + bb.y);
        o1.x = __float2half_rn((v[i].z - mu) * rs * gg.z + bb.z);
        o1.y = __float2half_rn((v[i].w - mu) * rs * gg.w + bb.w);
        *(__half2*)&orow[c] = o0;
        *(__half2*)&orow[c + 2] = o1;
    }
}

// ---------------- common mma helpers ----------------
__device__ __forceinline__ float gelu_erf(float v) {
    return 0.5f * v * (1.f + erff(v * 0.70710678118654752f));
}
__device__ __forceinline__ void cp16(unsigned dst, const void* src, int srcBytes) {
    asm volatile("cp.async.cg.shared.global [%0], [%1], 16, %2;"
                 :: "r"(dst), "l"(src), "r"(srcBytes));
}
__device__ __forceinline__ void cp_commit() {
    asm volatile("cp.async.commit_group;");
}
template<int Nw>
__device__ __forceinline__ void cp_wait() {
    asm volatile("cp.async.wait_group %0;" :: "n"(Nw));
}
__device__ __forceinline__ void ldm4(unsigned* r, unsigned addr) {
    asm volatile("ldmatrix.sync.aligned.m8n8.x4.shared.b16 {%0,%1,%2,%3}, [%4];"
                 : "=r"(r[0]), "=r"(r[1]), "=r"(r[2]), "=r"(r[3]) : "r"(addr));
}
__device__ __forceinline__ void mma16816(float* c, const unsigned* a, unsigned b0, unsigned b1) {
    asm volatile(
        "mma.sync.aligned.m16n8k16.row.col.f32.f16.f16.f32 "
        "{%0,%1,%2,%3}, {%4,%5,%6,%7}, {%8,%9}, {%0,%1,%2,%3};"
        : "+f"(c[0]), "+f"(c[1]), "+f"(c[2]), "+f"(c[3])
        : "r"(a[0]), "r"(a[1]), "r"(a[2]), "r"(a[3]), "r"(b0), "r"(b1));
}

// ---------------- fp16 tensor-core GEMM, BM=128, 4-stage cp.async ----------------
#define H_SH 40
#define H_TILE (128 * H_SH)
#define H_STG (2 * H_TILE)
#define H_NSTAGE 4
#define H_SMEM_BYTES (H_NSTAGE * H_STG * 2)

// EPI: 0 = fp32 C; 1 = fp16 C (no bias); 2 = +bias, exact gelu, fp16 C;
//      3 = +bias +fp32 residual, fp32 C.
template<int EPI>
__global__ __launch_bounds__(256, 2) void hgemm(
    const __half* __restrict__ A, const __half* __restrict__ Bt,
    const float* __restrict__ bias, const float* __restrict__ res,
    void* __restrict__ Cv, int M, int N, int K)
{
    extern __shared__ __half smh[];
    unsigned sbase = (unsigned)__cvta_generic_to_shared(smh);

    int tid = threadIdx.x;
    int row0 = blockIdx.y * 128, col0 = blockIdx.x * 128;
    int warp = tid >> 5, lane = tid & 31;
    int wm = (warp & 3) * 32, wn = (warp >> 2) * 64;
    int gid = lane >> 2, tig = lane & 3;
    int within = lane & 7, sub = lane >> 3;

    int lr = tid >> 1;
    int lc0 = (tid & 1) * 2;

    const __half* Ag = A + (size_t)(row0 + lr) * K;
    const __half* Bg = Bt + (size_t)(col0 + lr) * K;
    bool bok = (col0 + lr) < N;

    float acc[2][8][4];
    #pragma unroll
    for (int t = 0; t < 2; ++t)
        #pragma unroll
        for (int u = 0; u < 8; ++u)
            #pragma unroll
            for (int v = 0; v < 4; ++v) acc[t][u][v] = 0.f;

    int KT = K >> 5;

    auto issue = [&](int kt) {
        int stg = kt & (H_NSTAGE - 1);
        int koff = kt * 32;
        unsigned abase = sbase + (stg * H_STG) * 2;
        unsigned bbase = abase + H_TILE * 2;
        #pragma unroll
        for (int s = 0; s < 2; ++s) {
            int c = lc0 + s;
            cp16(abase + (lr * H_SH + c * 8) * 2, Ag + koff + c * 8, 16);
            cp16(bbase + (lr * H_SH + c * 8) * 2, Bg + koff + c * 8, bok ? 16 : 0);
        }
        cp_commit();
    };

    issue(0);
    if (KT > 1) issue(1);
    if (KT > 2) issue(2);

    int a_off = (wm + (sub & 1) * 8 + within) * H_SH + (sub >> 1) * 8;
    int b_off = (wn + (sub >> 1) * 8 + within) * H_SH + (sub & 1) * 8;

    for (int kt = 0; kt < KT; ++kt) {
        if (kt + 2 <= KT - 1) cp_wait<2>(); else cp_wait<0>();
        __syncthreads();
        if (kt + 3 < KT) issue(kt + 3);

        unsigned abase = sbase + ((kt & (H_NSTAGE - 1)) * H_STG) * 2;
        unsigned bbase = abase + H_TILE * 2;

        #pragma unroll
        for (int ks = 0; ks < 2; ++ks) {
            int kb = ks * 16;
            unsigned aR[2][4], bR[4][4];
            #pragma unroll
            for (int t = 0; t < 2; ++t)
                ldm4(aR[t], abase + (a_off + t * 16 * H_SH + kb) * 2);
            #pragma unroll
            for (int u = 0; u < 4; ++u)
                ldm4(bR[u], bbase + (b_off + u * 16 * H_SH + kb) * 2);
            #pragma unroll
            for (int t = 0; t < 2; ++t)
                #pragma unroll
                for (int u8 = 0; u8 < 8; ++u8) {
                    int u4 = u8 >> 1, hi = u8 & 1;
                    mma16816(acc[t][u8], aR[t], bR[u4][hi * 2], bR[u4][hi * 2 + 1]);
                }
        }
    }

    #pragma unroll
    for (int t = 0; t < 2; ++t) {
        #pragma unroll
        for (int u = 0; u < 8; ++u) {
            int c = col0 + wn + u * 8 + tig * 2;
            if (c >= N) continue;
            int r0 = row0 + wm + t * 16 + gid;
            float v0 = acc[t][u][0], v1 = acc[t][u][1];
            float v2 = acc[t][u][2], v3 = acc[t][u][3];
            if (EPI >= 2) {
                float2 bb = *(const float2*)&bias[c];
                v0 += bb.x; v1 += bb.y; v2 += bb.x; v3 += bb.y;
            }
            if (EPI == 1 || EPI == 2) {
                __half* C = (__half*)Cv;
                __half2 o0, o1;
                if (EPI == 2) {
                    o0.x = __float2half_rn(gelu_erf(v0)); o0.y = __float2half_rn(gelu_erf(v1));
                    o1.x = __float2half_rn(gelu_erf(v2)); o1.y = __float2half_rn(gelu_erf(v3));
                } else {
                    o0 = __floats2half2_rn(v0, v1);
                    o1 = __floats2half2_rn(v2, v3);
                }
                *(__half2*)&C[(size_t)r0 * N + c] = o0;
                *(__half2*)&C[(size_t)(r0 + 8) * N + c] = o1;
            } else {
                float* C = (float*)Cv;
                if (EPI == 3) {
                    float2 ra = *(const float2*)&res[(size_t)r0 * N + c];
                    float2 rb = *(const float2*)&res[(size_t)(r0 + 8) * N + c];
                    v0 += ra.x; v1 += ra.y; v2 += rb.x; v3 += rb.y;
                }
                float2 o0; o0.x = v0; o0.y = v1;
                float2 o1; o1.x = v2; o1.y = v3;
                *(float2*)&C[(size_t)r0 * N + c] = o0;
                *(float2*)&C[(size_t)(r0 + 8) * N + c] = o1;
            }
        }
    }
}

// ---------------- Flash attention on mma.sync (shift-free softmax) ----------------
// qkv16 is fp16 with Q pre-scaled; staging is pure copies.
#define AQ_STRIDE 24
#define AV_STRIDE 1032
#define ATT_QS_H (256 * AQ_STRIDE)
#define ATT_KS_H (1024 * AQ_STRIDE)
#define ATT_VT_H (16 * AV_STRIDE)
#define ATT_SMEM ((ATT_QS_H + ATT_KS_H + ATT_VT_H) * 2)

__global__ __launch_bounds__(256, 2) void attn_kernel(const __half* __restrict__ qkv16,
                                                      __half* __restrict__ out)
{
    extern __shared__ __half asm_[];
    __half* Qs = asm_;
    __half* Ks = Qs + ATT_QS_H;
    __half* Vt = Ks + ATT_KS_H;
    unsigned qs_a = (unsigned)__cvta_generic_to_shared(Qs);
    unsigned ks_a = (unsigned)__cvta_generic_to_shared(Ks);
    unsigned vt_a = (unsigned)__cvta_generic_to_shared(Vt);

    int chunk = blockIdx.x, h = blockIdx.y, b = blockIdx.z;
    int tid = threadIdx.x;

    // ---- stage Q (already scaled fp16): 12 halves copy + 4 zeros ----
    {
        const __half* qp = qkv16 + (size_t)(b * NN + chunk * 256 + tid) * (3 * INNERD) + h * HEAD_D;
        uint2 a = *(const uint2*)(qp);
        uint2 bq = *(const uint2*)(qp + 4);
        uint2 c = *(const uint2*)(qp + 8);
        uint2* d = (uint2*)(Qs + tid * AQ_STRIDE);
        d[0] = a; d[1] = bq; d[2] = c;
        uint2 z; z.x = 0u; z.y = 0u;
        d[3] = z;
    }
    // ---- stage K (copy) and V^T (unpack) ----
    #pragma unroll
    for (int r = 0; r < 4; ++r) {
        int key = r * 256 + tid;
        const __half* base = qkv16 + (size_t)(b * NN + key) * (3 * INNERD);
        const __half* kp = base + INNERD + h * HEAD_D;
        const __half* vp = base + 2 * INNERD + h * HEAD_D;
        uint2 a = *(const uint2*)(kp);
        uint2 bk = *(const uint2*)(kp + 4);
        uint2 c = *(const uint2*)(kp + 8);
        uint2* d = (uint2*)(Ks + key * AQ_STRIDE);
        d[0] = a; d[1] = bk; d[2] = c;
        uint2 z; z.x = 0u; z.y = 0u;
        d[3] = z;
        uint2 va = *(const uint2*)(vp);
        uint2 vb = *(const uint2*)(vp + 4);
        uint2 vc = *(const uint2*)(vp + 8);
        const __half* vh = (const __half*)&va;
        #pragma unroll
        for (int dd = 0; dd < 4; ++dd) Vt[dd * AV_STRIDE + key] = vh[dd];
        vh = (const __half*)&vb;
        #pragma unroll
        for (int dd = 0; dd < 4; ++dd) Vt[(dd + 4) * AV_STRIDE + key] = vh[dd];
        vh = (const __half*)&vc;
        #pragma unroll
        for (int dd = 0; dd < 4; ++dd) Vt[(dd + 8) * AV_STRIDE + key] = vh[dd];
    }
    for (int idx = tid; idx < 2 * AV_STRIDE; idx += 256)
        *(__half2*)(Vt + 12 * AV_STRIDE + idx * 2) = __floats2half2_rn(0.f, 0.f);
    __syncthreads();

    int warp = tid >> 5, lane = tid & 31;
    int gid = lane >> 2, tig = lane & 3;
    int within = lane & 7, sub = lane >> 3;
    int wm = warp * 32;

    unsigned aQ[2][4];
    {
        int a_off = (wm + (sub & 1) * 8 + within) * AQ_STRIDE + (sub >> 1) * 8;
        ldm4(aQ[0], qs_a + a_off * 2);
        ldm4(aQ[1], qs_a + (a_off + 16 * AQ_STRIDE) * 2);
    }
    int bk_off = ((sub >> 1) * 8 + within) * AQ_STRIDE + (sub & 1) * 8;
    int bv_off = ((sub >> 1) * 8 + within) * AV_STRIDE + (sub & 1) * 8;

    float O[2][2][4];
    #pragma unroll
    for (int mt = 0; mt < 2; ++mt)
        #pragma unroll
        for (int nt = 0; nt < 2; ++nt)
            #pragma unroll
            for (int v = 0; v < 4; ++v) O[mt][nt][v] = 0.f;
    float rs[4] = {0.f, 0.f, 0.f, 0.f};

    for (int kb = 0; kb < NN / 16; ++kb) {
        unsigned bK[4], bV[4];
        ldm4(bK, ks_a + (bk_off + kb * 16 * AQ_STRIDE) * 2);
        ldm4(bV, vt_a + (bv_off + kb * 16) * 2);

        float S[2][2][4];
        #pragma unroll
        for (int mt = 0; mt < 2; ++mt)
            #pragma unroll
            for (int nt = 0; nt < 2; ++nt) {
                S[mt][nt][0] = S[mt][nt][1] = S[mt][nt][2] = S[mt][nt][3] = 0.f;
                mma16816(S[mt][nt], aQ[mt], bK[nt * 2], bK[nt * 2 + 1]);
            }

        #pragma unroll
        for (int mt = 0; mt < 2; ++mt) {
            unsigned aP[4];
            float e00 = __expf(S[mt][0][0]), e01 = __expf(S[mt][0][1]);
            float e02 = __expf(S[mt][0][2]), e03 = __expf(S[mt][0][3]);
            float e10 = __expf(S[mt][1][0]), e11 = __expf(S[mt][1][1]);
            float e12 = __expf(S[mt][1][2]), e13 = __expf(S[mt][1][3]);
            rs[mt * 2 + 0] += (e00 + e01) + (e10 + e11);
            rs[mt * 2 + 1] += (e02 + e03) + (e12 + e13);
            __half2 p0 = __floats2half2_rn(e00, e01);
            __half2 p1 = __floats2half2_rn(e02, e03);
            __half2 p2 = __floats2half2_rn(e10, e11);
            __half2 p3 = __floats2half2_rn(e12, e13);
            aP[0] = *(unsigned*)&p0;
            aP[1] = *(unsigned*)&p1;
            aP[2] = *(unsigned*)&p2;
            aP[3] = *(unsigned*)&p3;
            mma16816(O[mt][0], aP, bV[0], bV[1]);
            mma16816(O[mt][1], aP, bV[2], bV[3]);
        }
    }

    #pragma unroll
    for (int i = 0; i < 4; ++i) {
        rs[i] += __shfl_xor_sync(0xFFFFFFFFu, rs[i], 1);
        rs[i] += __shfl_xor_sync(0xFFFFFFFFu, rs[i], 2);
    }
    float inv0 = 1.f / rs[0], inv1 = 1.f / rs[1];
    float inv2 = 1.f / rs[2], inv3 = 1.f / rs[3];

    #pragma unroll
    for (int mt = 0; mt < 2; ++mt) {
        float ia = mt ? inv2 : inv0;
        float ib = mt ? inv3 : inv1;
        int r0 = chunk * 256 + wm + mt * 16 + gid;
        __half* oa = out + (size_t)(b * NN + r0) * INNERD + h * HEAD_D;
        __half* ob = out + (size_t)(b * NN + r0 + 8) * INNERD + h * HEAD_D;
        int d0 = 2 * tig;
        *(__half2*)(oa + d0) = __floats2half2_rn(O[mt][0][0] * ia, O[mt][0][1] * ia);
        *(__half2*)(ob + d0) = __floats2half2_rn(O[mt][0][2] * ib, O[mt][0][3] * ib);
        if (tig < 2) {
            int d1 = 8 + 2 * tig;
            *(__half2*)(oa + d1) = __floats2half2_rn(O[mt][1][0] * ia, O[mt][1][1] * ia);
            *(__half2*)(ob + d1) = __floats2half2_rn(O[mt][1][2] * ib, O[mt][1][3] * ib);
        }
    }
}

// ---------------- launch ----------------
extern "C" void kernel_launch(void* const* d_in, const int* in_sizes, int n_in,
                              void* d_out, int out_size)
{
    const float* x     = (const float*)d_in[0];
    const float* ln1g  = (const float*)d_in[3];
    const float* ln1b  = (const float*)d_in[4];
    const float* wqkv  = (const float*)d_in[5];
    const float* wproj = (const float*)d_in[6];
    const float* bproj = (const float*)d_in[7];
    const float* ln2g  = (const float*)d_in[8];
    const float* ln2b  = (const float*)d_in[9];
    const float* w1    = (const float*)d_in[10];
    const float* b1    = (const float*)d_in[11];
    const float* w2    = (const float*)d_in[12];
    const float* b2    = (const float*)d_in[13];
    float* out = (float*)d_out;

    __half *h16, *qkv16, *att16, *mlp16, *wqkv_t, *wproj_t, *w1_t, *w2_t;
    float *x1;
    cudaGetSymbolAddress((void**)&h16,    g_h16);
    cudaGetSymbolAddress((void**)&qkv16,  g_qkv16);
    cudaGetSymbolAddress((void**)&att16,  g_att16);
    cudaGetSymbolAddress((void**)&x1,     g_x1);
    cudaGetSymbolAddress((void**)&mlp16,  g_mlp16);
    cudaGetSymbolAddress((void**)&wqkv_t, g_wqkv_t);
    cudaGetSymbolAddress((void**)&wproj_t,g_wproj_t);
    cudaGetSymbolAddress((void**)&w1_t,   g_w1_t);
    cudaGetSymbolAddress((void**)&w2_t,   g_w2_t);

    cudaFuncSetAttribute(hgemm<1>, cudaFuncAttributeMaxDynamicSharedMemorySize, H_SMEM_BYTES);
    cudaFuncSetAttribute(hgemm<2>, cudaFuncAttributeMaxDynamicSharedMemorySize, H_SMEM_BYTES);
    cudaFuncSetAttribute(hgemm<3>, cudaFuncAttributeMaxDynamicSharedMemorySize, H_SMEM_BYTES);
    cudaFuncSetAttribute(attn_kernel, cudaFuncAttributeMaxDynamicSharedMemorySize, ATT_SMEM);

    cudaStream_t cap = 0;

    static cudaStream_t s2 = nullptr;
    static cudaEvent_t evFork = nullptr, evJoin = nullptr;
    if (!s2) {
        cudaStreamCreateWithFlags(&s2, cudaStreamNonBlocking);
        cudaEventCreateWithFlags(&evFork, cudaEventDisableTiming);
        cudaEventCreateWithFlags(&evJoin, cudaEventDisableTiming);
    }

    cudaEventRecord(evFork, cap);
    cudaStreamWaitEvent(s2, evFork, 0);
    wconv_all<<<4896, 256, 0, s2>>>(wqkv, wqkv_t, wproj, wproj_t, w1, w1_t, w2, w2_t);
    cudaEventRecord(evJoin, s2);

    // 1) LN1 -> h16 (warp-per-row; parallel with wconv_all)
    ln_kernel<<<ROWS / 8, 256, 0, cap>>>(x, ln1g, ln1b, h16);

    cudaStreamWaitEvent(cap, evJoin, 0);

    // 2) QKV GEMM -> fp16 qkv (Q pre-scaled via weights)
    hgemm<1><<<dim3(3, ROWS / 128), 256, H_SMEM_BYTES, cap>>>(
        h16, wqkv_t, nullptr, nullptr, qkv16, ROWS, 3 * INNERD, EMBD);

    // 3) flash attention (mma) -> att16
    attn_kernel<<<dim3(NN / 256, HEADS, BB), 256, ATT_SMEM, cap>>>(qkv16, att16);

    // 4) proj GEMM + bias + residual(x) -> x1 fp32
    hgemm<3><<<dim3(EMBD / 128, ROWS / 128), 256, H_SMEM_BYTES, cap>>>(
        att16, wproj_t, bproj, x, x1, ROWS, EMBD, INNERD);

    // 5) LN2 -> h16 (warp-per-row)
    ln_kernel<<<ROWS / 8, 256, 0, cap>>>(x1, ln2g, ln2b, h16);

    // 6) MLP1 + bias + exact gelu -> mlp16
    hgemm<2><<<dim3(MLP_D / 128, ROWS / 128), 256, H_SMEM_BYTES, cap>>>(
        h16, w1_t, b1, nullptr, mlp16, ROWS, MLP_D, EMBD);

    // 7) MLP2 + bias + residual(x1) -> d_out fp32
    hgemm<3><<<dim3(EMBD / 128, ROWS / 128), 256, H_SMEM_BYTES, cap>>>(
        mlp16, w2_t, b2, x1, out, ROWS, EMBD, MLP_D);
}